// round 12
// baseline (speedup 1.0000x reference)
#include <cuda_runtime.h>
#include <cuda_fp16.h>

#define BB 8
#define HH 512
#define WW 512
#define HW (HH * WW)

#define NW 8                    // warps per block
#define WTW 32                  // warp tile width
#define WTH 8                   // warp tile height
#define SWC 38                  // halo cols
#define SHR 14                  // halo rows
#define RP 38                   // row pitch (halves)
// per-warp smem layout (halves): A_p=0, B_p=544, A_t=1088, B_t=1632
// B offsets chosen so (B - A) = 1088 bytes ... 1088*? -> 544h = 1088B == 64 mod 128:
// even lanes (copyA) hit banks 0-15, odd lanes (copyB) banks 16-31 -> conflict-free.
#define OFF_BP 544
#define OFF_AT 1088
#define OFF_BT 1632
#define WSTRIDE 2176            // halves per warp (4352 B)
#define NBLOCKS ((WW / WTW) * (HH / (NW * WTH)) * BB)   // 16*8*8 = 1024

__device__ unsigned long long g_pack = 0ULL;

__device__ __forceinline__ unsigned gt2(unsigned a, unsigned b) {
    return __hgt2_mask(*(const __half2*)&a, *(const __half2*)&b);
}

__global__ __launch_bounds__(NW * 32, 6)
void census_fused(const float* __restrict__ pred, const float* __restrict__ tgt,
                  float* __restrict__ out) {
    __shared__ __align__(16) unsigned short sm[NW * WSTRIDE];
    __shared__ int wsum[NW];

    const int b    = blockIdx.z;
    const int w    = threadIdx.x >> 5;
    const int lane = threadIdx.x & 31;
    const int x0   = blockIdx.x * WTW;
    const int y0w  = blockIdx.y * (NW * WTH) + w * WTH;   // this warp's tile top
    const int wb   = w * WSTRIDE;

    const float* __restrict__ pb = pred + (size_t)b * 3 * HW;
    const float* __restrict__ tb = tgt  + (size_t)b * 3 * HW;

    // ---- per-warp halo load + RGB->gray -> fp16, reflect padding, dual copies ----
    for (int e = lane; e < SHR * SWC; e += 32) {
        int ly = e / SWC;
        int lx = e - ly * SWC;
        int gy = y0w + ly - 3;
        gy = (gy < 0) ? -gy : ((gy >= HH) ? 2 * HH - 2 - gy : gy);
        int gx = x0 + lx - 3;
        gx = (gx < 0) ? -gx : ((gx >= WW) ? 2 * WW - 2 - gx : gx);
        int off = gy * WW + gx;
        float gp = fmaf(0.299f, pb[off], fmaf(0.587f, pb[HW + off], 0.114f * pb[2 * HW + off]));
        float gt = fmaf(0.299f, tb[off], fmaf(0.587f, tb[HW + off], 0.114f * tb[2 * HW + off]));
        unsigned short hp = __half_as_ushort(__float2half_rn(gp));
        unsigned short ht = __half_as_ushort(__float2half_rn(gt));
        int ib = ly * RP + lx;
        sm[wb + ib] = hp;                   // pred copyA
        sm[wb + OFF_AT + ib] = ht;          // tgt  copyA
        if (lx > 0) {                       // copyB: logical elem lx stored at lx-1
            sm[wb + OFF_BP + ib - 1] = hp;
            sm[wb + OFF_BT + ib - 1] = ht;
        }
    }
    __syncwarp();

    // ---- warp-autonomous census (no block barrier) ----
    const int coff = (lane & 1) ? OFF_BP : 0;   // shifted copy for odd lanes
    const int bhx  = lane & ~1;

    unsigned cp2[WTH], ct2[WTH];
#pragma unroll
    for (int k = 0; k < WTH; k++) {
        int ci = (k + 3) * RP + lane + 3;
        cp2[k] = (unsigned)sm[wb + ci] * 0x00010001u;
        ct2[k] = (unsigned)sm[wb + OFF_AT + ci] * 0x00010001u;
    }

    unsigned accM = 0, accA = 0;    // SIMD 16-bit field accumulators
#pragma unroll
    for (int r = 0; r < SHR; r++) {
        const int rb = wb + coff + r * RP + bhx;
        unsigned vp[4], vt[4];
#pragma unroll
        for (int i = 0; i < 4; i++) {
            vp[i] = *(const unsigned*)&sm[rb + 2 * i];
            vt[i] = *(const unsigned*)&sm[rb + OFF_AT + 2 * i];
        }
#pragma unroll
        for (int k = 0; k < WTH; k++) {
            const int dy = r - 3 - k;
            if (dy < -3 || dy > 3) continue;        // compile-time pruned
            unsigned x0m = gt2(cp2[k], vp[0]) ^ gt2(ct2[k], vt[0]);
            unsigned x1m = gt2(cp2[k], vp[1]) ^ gt2(ct2[k], vt[1]);
            unsigned x2m = gt2(cp2[k], vp[2]) ^ gt2(ct2[k], vt[2]);
            unsigned x3m = gt2(cp2[k], vp[3]) ^ gt2(ct2[k], vt[3]);
            accM = __vsub2(accM, x0m);   // 0xFFFF field == -1 -> +1 per mismatch
            accM = __vsub2(accM, x1m);
            accM = __vsub2(accM, x2m);
            accA = __vsub2(accA, x3m);   // lane1 (dx=+4) invalid -> hi field discarded
            // center self-compare (dy==0, dx==0 lane) is 0 automatically
        }
    }
    int cnt = (int)(accM & 0xFFFFu) + (int)(accM >> 16) + (int)(accA & 0xFFFFu);

    cnt = __reduce_add_sync(0xffffffffu, cnt);
    if (lane == 0) wsum[w] = cnt;
    __syncthreads();                     // only barrier: final reduction

    if (threadIdx.x == 0) {
        int v = 0;
#pragma unroll
        for (int i = 0; i < NW; i++) v += wsum[i];
        unsigned long long old =
            atomicAdd(&g_pack, (unsigned long long)v + (1ULL << 40));
        if ((old >> 40) == NBLOCKS - 1) {
            unsigned long long tot = (old & ((1ULL << 40) - 1)) + (unsigned long long)v;
            const double denom = 48.0 * (double)BB * (double)HW;  // 100663296
            out[0] = (float)((double)tot / denom);
            g_pack = 0ULL;               // reset for next graph replay
        }
    }
}

extern "C" void kernel_launch(void* const* d_in, const int* in_sizes, int n_in,
                              void* d_out, int out_size) {
    const float* pred = (const float*)d_in[0];
    const float* tgt  = (const float*)d_in[1];
    float* out = (float*)d_out;
    (void)in_sizes; (void)n_in; (void)out_size;

    dim3 bdim(NW * 32);
    dim3 gdim(WW / WTW, HH / (NW * WTH), BB);
    census_fused<<<gdim, bdim>>>(pred, tgt, out);
}

// round 13
// speedup vs baseline: 1.2349x; 1.2349x over previous
#include <cuda_runtime.h>
#include <cuda_fp16.h>

#define BB 8
#define HH 512
#define WW 512
#define HW (HH * WW)

#define TX 32
#define TYW 4                  // 128 threads
#define PY 8                   // rows per chunk
#define CHUNKS 2               // 16 rows per thread total
#define TILE_H (TYW * PY * CHUNKS)   // 64
#define SW (TX + 6)            // 38
#define SH (TILE_H + 6)        // 70
#define PITCH 40               // halves per smem row
#define CPY 2848               // halves per copy; CPY%64==32 -> copyB bank-shifted by 64B
#define NBLOCKS ((WW / TX) * (HH / TILE_H) * BB)   // 16*8*8 = 1024

__device__ unsigned long long g_pack = 0ULL;

__device__ __forceinline__ unsigned gt2(unsigned a, unsigned b) {
    return __hgt2_mask(*(const __half2*)&a, *(const __half2*)&b);
}

__global__ __launch_bounds__(TX * TYW, 7)
void census_fused(const float* __restrict__ pred, const float* __restrict__ tgt,
                  float* __restrict__ out) {
    // predA @0, predB @CPY (shifted 1 elem), tgtA @2*CPY, tgtB @3*CPY
    __shared__ __align__(16) unsigned short sm[4 * CPY];
    __shared__ int wsum[TYW];

    const int b  = blockIdx.z;
    const int x0 = blockIdx.x * TX;
    const int y0 = blockIdx.y * TILE_H;
    const int tid = threadIdx.y * TX + threadIdx.x;

    const float* __restrict__ pb = pred + (size_t)b * 3 * HW;
    const float* __restrict__ tb = tgt  + (size_t)b * 3 * HW;

    // Halo load + fused RGB->gray -> fp16, reflect padding, dual shifted copies.
    for (int idx = tid; idx < SH * SW; idx += TX * TYW) {
        int ly = idx / SW;
        int lx = idx - ly * SW;
        int gy = y0 + ly - 3;
        gy = (gy < 0) ? -gy : ((gy >= HH) ? 2 * HH - 2 - gy : gy);
        int gx = x0 + lx - 3;
        gx = (gx < 0) ? -gx : ((gx >= WW) ? 2 * WW - 2 - gx : gx);
        int off = gy * WW + gx;
        float gp = fmaf(0.299f, pb[off], fmaf(0.587f, pb[HW + off], 0.114f * pb[2 * HW + off]));
        float gt = fmaf(0.299f, tb[off], fmaf(0.587f, tb[HW + off], 0.114f * tb[2 * HW + off]));
        unsigned short hp = __half_as_ushort(__float2half_rn(gp));
        unsigned short ht = __half_as_ushort(__float2half_rn(gt));
        int ib = ly * PITCH + lx;
        sm[ib] = hp;
        sm[2 * CPY + ib] = ht;
        if (lx > 0) {                       // copyB: logical elem lx at index lx-1
            sm[CPY + ib - 1] = hp;
            sm[3 * CPY + ib - 1] = ht;
        }
    }
    __syncthreads();

    const int tx   = threadIdx.x;
    const int coff = (tx & 1) * CPY;        // odd lanes use shifted copy
    const int bhx  = tx & ~1;

    int cnt = 0;
#pragma unroll 1
    for (int half = 0; half < CHUNKS; half++) {
        const int base = threadIdx.y * (PY * CHUNKS) + half * PY;

        unsigned cp2[PY], ct2[PY];
#pragma unroll
        for (int k = 0; k < PY; k++) {
            int ci = (base + k + 3) * PITCH + tx + 3;
            cp2[k] = (unsigned)sm[ci] * 0x00010001u;
            ct2[k] = (unsigned)sm[2 * CPY + ci] * 0x00010001u;
        }

        unsigned accM = 0, accA = 0;    // SIMD 16-bit field accumulators
#pragma unroll
        for (int r = 0; r < PY + 6; r++) {
            const int rb = (base + r) * PITCH + bhx + coff;
            unsigned vp[4], vt[4];
#pragma unroll
            for (int i = 0; i < 4; i++) {
                vp[i] = *(const unsigned*)&sm[rb + 2 * i];
                vt[i] = *(const unsigned*)&sm[2 * CPY + rb + 2 * i];
            }
#pragma unroll
            for (int k = 0; k < PY; k++) {
                const int dy = r - 3 - k;
                if (dy < -3 || dy > 3) continue;        // compile-time pruned
                unsigned x0m = gt2(cp2[k], vp[0]) ^ gt2(ct2[k], vt[0]);
                unsigned x1m = gt2(cp2[k], vp[1]) ^ gt2(ct2[k], vt[1]);
                unsigned x2m = gt2(cp2[k], vp[2]) ^ gt2(ct2[k], vt[2]);
                unsigned x3m = gt2(cp2[k], vp[3]) ^ gt2(ct2[k], vt[3]);
                accM = __vsub2(accM, x0m);   // 0xFFFF field == -1 -> +1 per mismatch
                accM = __vsub2(accM, x1m);
                accM = __vsub2(accM, x2m);
                accA = __vsub2(accA, x3m);   // hi lane (dx=+4) invalid -> discarded
                // center self-compare (dy==0, dx==0 lane) is 0 automatically
            }
        }
        cnt += (int)(accM & 0xFFFFu) + (int)(accM >> 16) + (int)(accA & 0xFFFFu);
    }

    // Warp + block reduction
    cnt = __reduce_add_sync(0xffffffffu, cnt);
    if (tx == 0) wsum[threadIdx.y] = cnt;
    __syncthreads();

    if (tid == 0) {
        int v = 0;
#pragma unroll
        for (int w = 0; w < TYW; w++) v += wsum[w];
        unsigned long long old =
            atomicAdd(&g_pack, (unsigned long long)v + (1ULL << 40));
        if ((old >> 40) == NBLOCKS - 1) {
            unsigned long long tot = (old & ((1ULL << 40) - 1)) + (unsigned long long)v;
            const double denom = 48.0 * (double)BB * (double)HW;  // 100663296
            out[0] = (float)((double)tot / denom);
            g_pack = 0ULL;    // reset for next graph replay
        }
    }
}

extern "C" void kernel_launch(void* const* d_in, const int* in_sizes, int n_in,
                              void* d_out, int out_size) {
    const float* pred = (const float*)d_in[0];
    const float* tgt  = (const float*)d_in[1];
    float* out = (float*)d_out;
    (void)in_sizes; (void)n_in; (void)out_size;

    dim3 bdim(TX, TYW);
    dim3 gdim(WW / TX, HH / TILE_H, BB);
    census_fused<<<gdim, bdim>>>(pred, tgt, out);
}

// round 14
// speedup vs baseline: 1.4548x; 1.1780x over previous
#include <cuda_runtime.h>
#include <cuda_fp16.h>

#define BB 8
#define HH 512
#define WW 512
#define HW (HH * WW)

#define TX 32
#define TYW 8                  // 256 threads
#define PY 8
#define TILE_H (TYW * PY)      // 64
#define SW 38                  // logical halo cols
#define SH (TILE_H + 6)        // 70
#define PITCH 40               // storage cols per row (si = 0..39)
#define CPY 2848               // halves per copy; copyB bank-shifted 64B vs copyA
#define NBLOCKS ((WW / TX) * (HH / TILE_H) * BB)   // 1024
#define NPAIR (SH * 20)        // 1400 pair-elements (fast path)

__device__ unsigned long long g_pack = 0ULL;

__device__ __forceinline__ unsigned gt2(unsigned a, unsigned b) {
    return __hgt2_mask(*(const __half2*)&a, *(const __half2*)&b);
}

__global__ __launch_bounds__(TX * TYW, 5)
void census_fused(const float* __restrict__ pred, const float* __restrict__ tgt,
                  float* __restrict__ out) {
    // predA @0, predB @CPY (copyB[i] = elem si i+1), tgtA @2*CPY, tgtB @3*CPY
    __shared__ __align__(16) unsigned short sm[4 * CPY];
    __shared__ int wsum[TYW];

    const int b  = blockIdx.z;
    const int x0 = blockIdx.x * TX;
    const int y0 = blockIdx.y * TILE_H;
    const int tid = threadIdx.y * TX + threadIdx.x;

    const float* __restrict__ pb = pred + (size_t)b * 3 * HW;
    const float* __restrict__ tb = tgt  + (size_t)b * 3 * HW;

    const bool interiorBlk = (blockIdx.x > 0 && blockIdx.x + 1 < gridDim.x &&
                              blockIdx.y > 0 && blockIdx.y + 1 < gridDim.y);

    if (interiorBlk) {
        // -------- fast halo: float2 pair loads, no reflect, fixed 6 iters --------
        const int ax0 = x0 - 4;             // 8B-aligned pair start
#pragma unroll
        for (int it = 0; it < 6; it++) {
            int q = tid + it * (TX * TYW);
            if (q < NPAIR) {
                int ly = q / 20;
                int p  = q - ly * 20;       // pair index 0..19
                int off = (y0 + ly - 3) * WW + ax0 + 2 * p;
                float2 pr = *(const float2*)(pb + off);
                float2 pg = *(const float2*)(pb + HW + off);
                float2 pbch = *(const float2*)(pb + 2 * HW + off);
                float2 tr = *(const float2*)(tb + off);
                float2 tg = *(const float2*)(tb + HW + off);
                float2 tbch = *(const float2*)(tb + 2 * HW + off);
                float gp0 = fmaf(0.299f, pr.x, fmaf(0.587f, pg.x, 0.114f * pbch.x));
                float gp1 = fmaf(0.299f, pr.y, fmaf(0.587f, pg.y, 0.114f * pbch.y));
                float gt0 = fmaf(0.299f, tr.x, fmaf(0.587f, tg.x, 0.114f * tbch.x));
                float gt1 = fmaf(0.299f, tr.y, fmaf(0.587f, tg.y, 0.114f * tbch.y));
                __half2 hp = __floats2half2_rn(gp0, gp1);
                __half2 ht = __floats2half2_rn(gt0, gt1);
                int e = ly * PITCH + 2 * p;              // si of pair lo elem (even)
                *(unsigned*)&sm[e] = *(unsigned*)&hp;                 // copyA u32
                *(unsigned*)&sm[2 * CPY + e] = *(unsigned*)&ht;
                // copyB[i] = elem i+1:  [e-1]=lo, [e]=hi
                if (p > 0) {
                    sm[CPY + e - 1]     = __half_as_ushort(__low2half(hp));
                    sm[3 * CPY + e - 1] = __half_as_ushort(__low2half(ht));
                }
                sm[CPY + e]     = __half_as_ushort(__high2half(hp));
                sm[3 * CPY + e] = __half_as_ushort(__high2half(ht));
            }
        }
    } else {
        // -------- border halo: scalar loads with reflect padding --------
        for (int idx = tid; idx < SH * SW; idx += TX * TYW) {
            int ly = idx / SW;
            int lx = idx - ly * SW;
            int gy = y0 + ly - 3;
            gy = (gy < 0) ? -gy : ((gy >= HH) ? 2 * HH - 2 - gy : gy);
            int gx = x0 + lx - 3;
            gx = (gx < 0) ? -gx : ((gx >= WW) ? 2 * WW - 2 - gx : gx);
            int off = gy * WW + gx;
            float gp = fmaf(0.299f, pb[off], fmaf(0.587f, pb[HW + off], 0.114f * pb[2 * HW + off]));
            float gt = fmaf(0.299f, tb[off], fmaf(0.587f, tb[HW + off], 0.114f * tb[2 * HW + off]));
            unsigned short hp = __half_as_ushort(__float2half_rn(gp));
            unsigned short ht = __half_as_ushort(__float2half_rn(gt));
            int si = lx + 1;                 // storage index (0 and 39 unused/unread)
            int ib = ly * PITCH + si;
            sm[ib] = hp;
            sm[2 * CPY + ib] = ht;
            sm[CPY + ib - 1] = hp;           // copyB[si-1] = elem si
            sm[3 * CPY + ib - 1] = ht;
        }
    }
    __syncthreads();

    // -------- census core (R11, shifted: window col j <-> si = tx+1+j) --------
    const int tx   = threadIdx.x;
    const int base = threadIdx.y * PY;
    const int s    = tx + 1;                 // window start si
    const int coff = (s & 1) * CPY;          // odd start -> shifted copy
    const int bhx  = s & ~1;

    unsigned cp2[PY], ct2[PY];
#pragma unroll
    for (int k = 0; k < PY; k++) {
        int ci = (base + k + 3) * PITCH + tx + 4;   // center si = tx+4
        cp2[k] = (unsigned)sm[ci] * 0x00010001u;
        ct2[k] = (unsigned)sm[2 * CPY + ci] * 0x00010001u;
    }

    unsigned accM = 0, accA = 0;    // SIMD 16-bit field accumulators
#pragma unroll
    for (int r = 0; r < PY + 6; r++) {
        const int rb = (base + r) * PITCH + bhx + coff;
        unsigned vp[4], vt[4];
#pragma unroll
        for (int i = 0; i < 4; i++) {
            vp[i] = *(const unsigned*)&sm[rb + 2 * i];
            vt[i] = *(const unsigned*)&sm[2 * CPY + rb + 2 * i];
        }
#pragma unroll
        for (int k = 0; k < PY; k++) {
            const int dy = r - 3 - k;
            if (dy < -3 || dy > 3) continue;        // compile-time pruned
            unsigned x0m = gt2(cp2[k], vp[0]) ^ gt2(ct2[k], vt[0]);
            unsigned x1m = gt2(cp2[k], vp[1]) ^ gt2(ct2[k], vt[1]);
            unsigned x2m = gt2(cp2[k], vp[2]) ^ gt2(ct2[k], vt[2]);
            unsigned x3m = gt2(cp2[k], vp[3]) ^ gt2(ct2[k], vt[3]);
            accM = __vsub2(accM, x0m);   // 0xFFFF field == -1 -> +1 per mismatch
            accM = __vsub2(accM, x1m);
            accM = __vsub2(accM, x2m);
            accA = __vsub2(accA, x3m);   // hi lane (dx=+4) invalid -> discarded
            // center self-compare (dy==0, dx==0 lane) is 0 automatically
        }
    }
    int cnt = (int)(accM & 0xFFFFu) + (int)(accM >> 16) + (int)(accA & 0xFFFFu);

    // Warp + block reduction
    cnt = __reduce_add_sync(0xffffffffu, cnt);
    if (tx == 0) wsum[threadIdx.y] = cnt;
    __syncthreads();

    if (tid == 0) {
        int v = 0;
#pragma unroll
        for (int w = 0; w < TYW; w++) v += wsum[w];
        unsigned long long old =
            atomicAdd(&g_pack, (unsigned long long)v + (1ULL << 40));
        if ((old >> 40) == NBLOCKS - 1) {
            unsigned long long tot = (old & ((1ULL << 40) - 1)) + (unsigned long long)v;
            const double denom = 48.0 * (double)BB * (double)HW;  // 100663296
            out[0] = (float)((double)tot / denom);
            g_pack = 0ULL;    // reset for next graph replay
        }
    }
}

extern "C" void kernel_launch(void* const* d_in, const int* in_sizes, int n_in,
                              void* d_out, int out_size) {
    const float* pred = (const float*)d_in[0];
    const float* tgt  = (const float*)d_in[1];
    float* out = (float*)d_out;
    (void)in_sizes; (void)n_in; (void)out_size;

    dim3 bdim(TX, TYW);
    dim3 gdim(WW / TX, HH / TILE_H, BB);
    census_fused<<<gdim, bdim>>>(pred, tgt, out);
}